// round 8
// baseline (speedup 1.0000x reference)
#include <cuda_runtime.h>
#include <math.h>
#include <float.h>

// Problem geometry
#define NDIR   1986
#define NV     64
#define NBP    128     // B*P = 8*16
#define TPB    128
#define NCH    8       // 8 blocks x 256 dirs (2 per thread) = 2048 >= 1986

// Output layout (float element offsets inside d_out)
#define OFF_POINTS 0
#define OFF_DH     762624
#define OFF_OVER   1779456
#define OFF_MEAN   1779584
#define OFF_DIRS   1779968
#define OFF_LV     1785926

__constant__ float c_pow10[21] = {
    1e0f, 1e1f, 1e2f, 1e3f, 1e4f, 1e5f, 1e6f, 1e7f, 1e8f, 1e9f, 1e10f,
    1e11f, 1e12f, 1e13f, 1e14f, 1e15f, 1e16f, 1e17f, 1e18f, 1e19f, 1e20f
};

// f64->f32-cast trig at cancellation angles
#define COS_HALFPI  6.123234e-17f
#define SIN_NEGPI  -1.2246468e-16f

// ---- packed f32x2 helpers (sm_103a FFMA2 path) ----
typedef unsigned long long u64;
__device__ __forceinline__ u64 pk2(float lo, float hi) {
    u64 r; asm("mov.b64 %0, {%1, %2};" : "=l"(r) : "f"(lo), "f"(hi)); return r;
}
__device__ __forceinline__ void upk2(u64 v, float& lo, float& hi) {
    asm("mov.b64 {%0, %1}, %2;" : "=f"(lo), "=f"(hi) : "l"(v));
}
__device__ __forceinline__ u64 fma2(u64 a, u64 b, u64 c) {
    u64 d; asm("fma.rn.f32x2 %0, %1, %2, %3;" : "=l"(d) : "l"(a), "l"(b), "l"(c)); return d;
}
__device__ __forceinline__ u64 mul2(u64 a, u64 b) {
    u64 d; asm("mul.rn.f32x2 %0, %1, %2;" : "=l"(d) : "l"(a), "l"(b)); return d;
}
__device__ __forceinline__ u64 add2(u64 a, u64 b) {
    u64 d; asm("add.rn.f32x2 %0, %1, %2;" : "=l"(d) : "l"(a), "l"(b)); return d;
}

__device__ __forceinline__ void make_dir(int d, float& dx, float& dy, float& dz) {
    const float STEP = 0.09817477042468103f;   // pi/32
    const float NPI  = -3.14159265358979323846f;
    const float NPI2 = -1.57079632679489662f;
    float c1, s1, c2, s2;
    if (d >= 1984) {
        c1 = COS_HALFPI;
        s1 = (d == 1984) ? -1.0f : 1.0f;
        c2 = -1.0f;
        s2 = SIN_NEGPI;
    } else {
        int i = (d >> 6) + 1;
        int j = d & 63;
        __sincosf(fmaf((float)i, STEP, NPI2), &s1, &c1);
        if (j == 0)       { c2 = -1.0f;       s2 = SIN_NEGPI; }
        else if (j == 16) { c2 = COS_HALFPI;  s2 = -1.0f; }
        else if (j == 48) { c2 = COS_HALFPI;  s2 = 1.0f; }
        else              { __sincosf(fmaf((float)j, STEP, NPI), &s2, &c2); }
    }
    dx = c1 * c2;
    dy = c1 * s2;
    dz = s1;
}

// Cold path: redo one direction with the proper scale factor k (k != 1).
// sxyf: interleaved (x_v, x_v1, y_v, y_v1) quads; szf: z array.
__device__ __noinline__ void redo_dir(const float* sxyf, const float* szf,
                                      float pm1, float k,
                                      float dx, float dy, float dz,
                                      float& sum, float& wx, float& wy, float& wz) {
    sum = 0.0f; wx = 0.0f; wy = 0.0f; wz = 0.0f;
    for (int v = 0; v < NV; v++) {
        float x = sxyf[(v >> 1) * 4 + (v & 1)];
        float y = sxyf[(v >> 1) * 4 + 2 + (v & 1)];
        float z = szf[v];
        float zr  = fmaf(x, dx, fmaf(y, dy, z * dz));
        float zms = fmaxf(zr, 0.0f) * k;
        float l   = __log2f(zms);
        float w   = exp2f(pm1 * l);
        float zp  = fminf(fmaxf(w * zms, 1e-20f), 1e20f);
        sum += (zr > 0.0f) ? zp : 0.0f;
        wx = fmaf(w, x, wx);
        wy = fmaf(w, y, wy);
        wz = fmaf(w, z, wz);
    }
}

// ---------------------------------------------------------------------------
// Fused single-loop kernel: grid (NCH, NBP), 128 threads, 2 dirs/thread.
// Speculates k=1 (checked after the loop; rare exact redo path otherwise).
// Vertex pairs processed with packed f32x2 FMA.
// ---------------------------------------------------------------------------
__global__ __launch_bounds__(TPB)
void fused_kernel(const float* __restrict__ verts,
                  const float* __restrict__ smooth,
                  float* __restrict__ out) {
    __shared__ float4 sxy[NV / 2];   // (x_v, x_v1, y_v, y_v1)
    __shared__ float2 szz[NV / 2];   // (z_v, z_v1)
    __shared__ float  sred[6];
    __shared__ float  smean[3];

    const int bp  = blockIdx.y;
    const int tid = threadIdx.x;
    const int d0  = blockIdx.x * (2 * TPB) + tid;
    const int d1  = d0 + TPB;

    // ---- prologue: mean + local_v into paired smem layout ----
    float px = 0.f, py = 0.f, pz = 0.f;
    if (tid < NV) {
        const float* vp = verts + (bp * NV + tid) * 3;
        px = vp[0]; py = vp[1]; pz = vp[2];
    }
    {
        float sx = px, sy = py, sz = pz;
        #pragma unroll
        for (int o = 16; o > 0; o >>= 1) {
            sx += __shfl_down_sync(0xffffffffu, sx, o);
            sy += __shfl_down_sync(0xffffffffu, sy, o);
            sz += __shfl_down_sync(0xffffffffu, sz, o);
        }
        int warp = tid >> 5, lane = tid & 31;
        if (warp < 2 && lane == 0) {
            sred[warp * 3 + 0] = sx;
            sred[warp * 3 + 1] = sy;
            sred[warp * 3 + 2] = sz;
        }
    }
    __syncthreads();
    if (tid == 0) {
        smean[0] = (sred[0] + sred[3]) * (1.0f / 64.0f);
        smean[1] = (sred[1] + sred[4]) * (1.0f / 64.0f);
        smean[2] = (sred[2] + sred[5]) * (1.0f / 64.0f);
    }
    __syncthreads();
    const float mx = smean[0], my = smean[1], mz = smean[2];
    float lx = px - mx, ly = py - my, lz = pz - mz;
    if (tid < NV) {
        float* xyf = (float*)sxy;
        xyf[(tid >> 1) * 4 + (tid & 1)]     = lx;
        xyf[(tid >> 1) * 4 + 2 + (tid & 1)] = ly;
        ((float*)szz)[tid]                  = lz;
    }
    __syncthreads();

    // ---- aux per-bp outputs ----
    if (blockIdx.x == 0) {
        if (tid == 0) {
            out[OFF_MEAN + bp * 3 + 0] = mx;
            out[OFF_MEAN + bp * 3 + 1] = my;
            out[OFF_MEAN + bp * 3 + 2] = mz;
            out[OFF_OVER + bp] = 0.0f;
        }
        if (tid < NV) {
            int idx = OFF_LV + (bp * NV + tid) * 3;
            out[idx + 0] = lx;
            out[idx + 1] = ly;
            out[idx + 2] = lz;
        }
    }

    // ---- directions ----
    float ax, ay, az, bxd, byd, bzd;
    make_dir(d0, ax, ay, az);
    make_dir(d1 < NDIR ? d1 : 0, bxd, byd, bzd);
    const bool has1 = (d1 < NDIR);

    if (blockIdx.y == 0) {
        out[OFF_DIRS + 3 * d0 + 0] = ax;
        out[OFF_DIRS + 3 * d0 + 1] = ay;
        out[OFF_DIRS + 3 * d0 + 2] = az;
        if (has1) {
            out[OFF_DIRS + 3 * d1 + 0] = bxd;
            out[OFF_DIRS + 3 * d1 + 1] = byd;
            out[OFF_DIRS + 3 * d1 + 2] = bzd;
        }
    }

    const float p   = __ldg(&smooth[bp]);
    const float pm1 = p - 1.0f;
    const u64 pm1_2 = pk2(pm1, pm1);
    const u64 axx = pk2(ax, ax),   ayy = pk2(ay, ay),   azz = pk2(az, az);
    const u64 bxx = pk2(bxd, bxd), byy = pk2(byd, byd), bzz = pk2(bzd, bzd);

    // ---- single fused loop (k=1 speculation), packed vertex pairs ----
    u64 suma = 0ull, wxa = 0ull, wya = 0ull, wza = 0ull;
    u64 sumb = 0ull, wxb = 0ull, wyb = 0ull, wzb = 0ull;
    float zmaxa = 0.0f, zmaxb = 0.0f;

    #pragma unroll 8
    for (int i = 0; i < NV / 2; i++) {
        float4 xy = sxy[i];
        float2 zz = szz[i];
        u64 xx = pk2(xy.x, xy.y);
        u64 yy = pk2(xy.z, xy.w);
        u64 zp = pk2(zz.x, zz.y);
        // dir a
        {
            u64 z2 = fma2(xx, axx, fma2(yy, ayy, mul2(zp, azz)));
            float ze, zo; upk2(z2, ze, zo);
            float zme = fmaxf(ze, 0.0f), zmo = fmaxf(zo, 0.0f);
            zmaxa = fmaxf(zmaxa, zme);
            zmaxa = fmaxf(zmaxa, zmo);
            float le = __log2f(zme), lo = __log2f(zmo);
            float te, to; upk2(mul2(pk2(le, lo), pm1_2), te, to);
            float we = exp2f(te), wo = exp2f(to);
            u64 w2 = pk2(we, wo);
            float zpe, zpo; upk2(mul2(w2, pk2(zme, zmo)), zpe, zpo);
            float fe = (ze > 0.0f) ? fmaxf(zpe, 1e-20f) : 0.0f;
            float fo = (zo > 0.0f) ? fmaxf(zpo, 1e-20f) : 0.0f;
            suma = add2(suma, pk2(fe, fo));
            wxa = fma2(w2, xx, wxa);
            wya = fma2(w2, yy, wya);
            wza = fma2(w2, zp, wza);
        }
        // dir b
        {
            u64 z2 = fma2(xx, bxx, fma2(yy, byy, mul2(zp, bzz)));
            float ze, zo; upk2(z2, ze, zo);
            float zme = fmaxf(ze, 0.0f), zmo = fmaxf(zo, 0.0f);
            zmaxb = fmaxf(zmaxb, zme);
            zmaxb = fmaxf(zmaxb, zmo);
            float le = __log2f(zme), lo = __log2f(zmo);
            float te, to; upk2(mul2(pk2(le, lo), pm1_2), te, to);
            float we = exp2f(te), wo = exp2f(to);
            u64 w2 = pk2(we, wo);
            float zpe, zpo; upk2(mul2(w2, pk2(zme, zmo)), zpe, zpo);
            float fe = (ze > 0.0f) ? fmaxf(zpe, 1e-20f) : 0.0f;
            float fo = (zo > 0.0f) ? fmaxf(zpo, 1e-20f) : 0.0f;
            sumb = add2(sumb, pk2(fe, fo));
            wxb = fma2(w2, xx, wxb);
            wyb = fma2(w2, yy, wyb);
            wzb = fma2(w2, zp, wzb);
        }
    }

    // ---- horizontal reduce ----
    float s0, t0, wx0, wy0, wz0, u0, u1, u2;
    upk2(suma, s0, t0); s0 += t0;
    upk2(wxa, wx0, u0); wx0 += u0;
    upk2(wya, wy0, u1); wy0 += u1;
    upk2(wza, wz0, u2); wz0 += u2;
    float s1, wx1, wy1, wz1;
    upk2(sumb, s1, t0); s1 += t0;
    upk2(wxb, wx1, u0); wx1 += u0;
    upk2(wyb, wy1, u1); wy1 += u1;
    upk2(wzb, wz1, u2); wz1 += u2;

    const float invp = 1.0f / p;
    const float omp  = 1.0f - p;
    const float* sxyf = (const float*)sxy;
    const float* szf  = (const float*)szz;

    // ---- k check + epilogue, dir 0 ----
    {
        float k0 = 1.0f;
        float h, scale;
        if (zmaxa > 0.0f) {
            float expo = log10f(zmaxa) * p;
            if (expo < -20.0f) {   // rare: redo with proper k
                float ke = fminf(fmaxf(ceilf((-20.0f - expo) / p), 0.0f), 20.0f);
                k0 = c_pow10[(int)ke];
                redo_dir(sxyf, szf, pm1, k0, ax, ay, az, s0, wx0, wy0, wz0);
            }
            h = exp2f(__log2f(s0) * invp);
            h = fminf(fmaxf(h, 1e-20f), 1e20f);
            scale = exp2f(omp * __log2f(h));
        } else {
            k0 = 1e20f; h = 1e-20f; scale = 0.0f;
            wx0 = wy0 = wz0 = 0.0f;
        }
        size_t pidx = ((size_t)bp * NDIR + d0) * 3;
        out[OFF_POINTS + pidx + 0] = fmaf(wx0, scale, mx);
        out[OFF_POINTS + pidx + 1] = fmaf(wy0, scale, my);
        out[OFF_POINTS + pidx + 2] = fmaf(wz0, scale, mz);
        ((float4*)(out + OFF_DH))[(size_t)bp * NDIR + d0] =
            make_float4(ax, ay, az, h / k0);
    }
    // ---- dir 1 ----
    if (has1) {
        float k1 = 1.0f;
        float h, scale;
        if (zmaxb > 0.0f) {
            float expo = log10f(zmaxb) * p;
            if (expo < -20.0f) {
                float ke = fminf(fmaxf(ceilf((-20.0f - expo) / p), 0.0f), 20.0f);
                k1 = c_pow10[(int)ke];
                redo_dir(sxyf, szf, pm1, k1, bxd, byd, bzd, s1, wx1, wy1, wz1);
            }
            h = exp2f(__log2f(s1) * invp);
            h = fminf(fmaxf(h, 1e-20f), 1e20f);
            scale = exp2f(omp * __log2f(h));
        } else {
            k1 = 1e20f; h = 1e-20f; scale = 0.0f;
            wx1 = wy1 = wz1 = 0.0f;
        }
        size_t pidx = ((size_t)bp * NDIR + d1) * 3;
        out[OFF_POINTS + pidx + 0] = fmaf(wx1, scale, mx);
        out[OFF_POINTS + pidx + 1] = fmaf(wy1, scale, my);
        out[OFF_POINTS + pidx + 2] = fmaf(wz1, scale, mz);
        ((float4*)(out + OFF_DH))[(size_t)bp * NDIR + d1] =
            make_float4(bxd, byd, bzd, h / k1);
    }
}

// ---------------------------------------------------------------------------
extern "C" void kernel_launch(void* const* d_in, const int* in_sizes, int n_in,
                              void* d_out, int out_size) {
    const float* verts  = (const float*)d_in[0];
    const float* smooth = (const float*)d_in[1];
    float* out = (float*)d_out;

    fused_kernel<<<dim3(NCH, NBP), TPB>>>(verts, smooth, out);
}

// round 10
// speedup vs baseline: 1.4349x; 1.4349x over previous
#include <cuda_runtime.h>
#include <math.h>
#include <float.h>

// Problem geometry
#define NDIR   1986
#define NV     64
#define NBP    128     // B*P = 8*16
#define TPB    128
#define NCH    8       // 8 blocks x 256 dirs (2 per thread) = 2048 >= 1986

// Output layout (float element offsets inside d_out)
#define OFF_POINTS 0
#define OFF_DH     762624
#define OFF_OVER   1779456
#define OFF_MEAN   1779584
#define OFF_DIRS   1779968
#define OFF_LV     1785926

__constant__ float c_pow10[21] = {
    1e0f, 1e1f, 1e2f, 1e3f, 1e4f, 1e5f, 1e6f, 1e7f, 1e8f, 1e9f, 1e10f,
    1e11f, 1e12f, 1e13f, 1e14f, 1e15f, 1e16f, 1e17f, 1e18f, 1e19f, 1e20f
};

// f64->f32-cast trig at cancellation angles
#define COS_HALFPI  6.123234e-17f
#define SIN_NEGPI  -1.2246468e-16f

__device__ __forceinline__ void make_dir(int d, float& dx, float& dy, float& dz) {
    const float STEP = 0.09817477042468103f;   // pi/32
    const float NPI  = -3.14159265358979323846f;
    const float NPI2 = -1.57079632679489662f;
    float c1, s1, c2, s2;
    if (d >= 1984) {
        c1 = COS_HALFPI;
        s1 = (d == 1984) ? -1.0f : 1.0f;
        c2 = -1.0f;
        s2 = SIN_NEGPI;
    } else {
        int i = (d >> 6) + 1;
        int j = d & 63;
        __sincosf(fmaf((float)i, STEP, NPI2), &s1, &c1);
        if (j == 0)       { c2 = -1.0f;       s2 = SIN_NEGPI; }
        else if (j == 16) { c2 = COS_HALFPI;  s2 = -1.0f; }
        else if (j == 48) { c2 = COS_HALFPI;  s2 = 1.0f; }
        else              { __sincosf(fmaf((float)j, STEP, NPI), &s2, &c2); }
    }
    dx = c1 * c2;
    dy = c1 * s2;
    dz = s1;
}

// Cold path: redo one direction with the proper scale factor k (k != 1).
__device__ __noinline__ void redo_dir(const float4* slv,
                                      float pm1, float k,
                                      float dx, float dy, float dz,
                                      float& sum, float& wx, float& wy, float& wz) {
    sum = 0.0f; wx = 0.0f; wy = 0.0f; wz = 0.0f;
    for (int v = 0; v < NV; v++) {
        float4 lv = slv[v];
        float z   = fmaf(lv.x, dx, fmaf(lv.y, dy, lv.z * dz));
        float zms = fmaxf(z, 0.0f) * k;
        float l   = __log2f(zms);
        float w   = exp2f(pm1 * l);
        float zp  = fminf(fmaxf(w * zms, 1e-20f), 1e20f);
        sum += (z > 0.0f) ? zp : 0.0f;
        wx = fmaf(w, lv.x, wx);
        wy = fmaf(w, lv.y, wy);
        wz = fmaf(w, lv.z, wz);
    }
}

// ---------------------------------------------------------------------------
// Fused single-loop kernel: grid (NCH, NBP), 128 threads, 2 dirs/thread.
// Speculates k=1 (post-checked exactly; rare cold redo otherwise).
// ---------------------------------------------------------------------------
__global__ __launch_bounds__(TPB)
void fused_kernel(const float* __restrict__ verts,
                  const float* __restrict__ smooth,
                  float* __restrict__ out) {
    __shared__ float4 slv[NV];
    __shared__ float  sred[6];
    __shared__ float  smean[3];

    const int bp  = blockIdx.y;
    const int tid = threadIdx.x;
    const int d0  = blockIdx.x * (2 * TPB) + tid;
    const int d1  = d0 + TPB;

    // ---- prologue: mean + local_v ----
    float px = 0.f, py = 0.f, pz = 0.f;
    if (tid < NV) {
        const float* vp = verts + (bp * NV + tid) * 3;
        px = vp[0]; py = vp[1]; pz = vp[2];
    }
    {
        float sx = px, sy = py, sz = pz;
        #pragma unroll
        for (int o = 16; o > 0; o >>= 1) {
            sx += __shfl_down_sync(0xffffffffu, sx, o);
            sy += __shfl_down_sync(0xffffffffu, sy, o);
            sz += __shfl_down_sync(0xffffffffu, sz, o);
        }
        int warp = tid >> 5, lane = tid & 31;
        if (warp < 2 && lane == 0) {
            sred[warp * 3 + 0] = sx;
            sred[warp * 3 + 1] = sy;
            sred[warp * 3 + 2] = sz;
        }
    }
    __syncthreads();
    if (tid == 0) {
        smean[0] = (sred[0] + sred[3]) * (1.0f / 64.0f);
        smean[1] = (sred[1] + sred[4]) * (1.0f / 64.0f);
        smean[2] = (sred[2] + sred[5]) * (1.0f / 64.0f);
    }
    __syncthreads();
    const float mx = smean[0], my = smean[1], mz = smean[2];
    if (tid < NV) {
        slv[tid] = make_float4(px - mx, py - my, pz - mz, 0.0f);
    }
    __syncthreads();

    // ---- aux per-bp outputs ----
    if (blockIdx.x == 0) {
        if (tid == 0) {
            out[OFF_MEAN + bp * 3 + 0] = mx;
            out[OFF_MEAN + bp * 3 + 1] = my;
            out[OFF_MEAN + bp * 3 + 2] = mz;
            out[OFF_OVER + bp] = 0.0f;
        }
        if (tid < NV) {
            float4 lv = slv[tid];
            int idx = OFF_LV + (bp * NV + tid) * 3;
            out[idx + 0] = lv.x;
            out[idx + 1] = lv.y;
            out[idx + 2] = lv.z;
        }
    }

    // ---- directions ----
    float ax, ay, az, bx, by, bz;
    make_dir(d0, ax, ay, az);
    make_dir(d1 < NDIR ? d1 : 0, bx, by, bz);
    const bool has1 = (d1 < NDIR);

    if (blockIdx.y == 0) {
        out[OFF_DIRS + 3 * d0 + 0] = ax;
        out[OFF_DIRS + 3 * d0 + 1] = ay;
        out[OFF_DIRS + 3 * d0 + 2] = az;
        if (has1) {
            out[OFF_DIRS + 3 * d1 + 0] = bx;
            out[OFF_DIRS + 3 * d1 + 1] = by;
            out[OFF_DIRS + 3 * d1 + 2] = bz;
        }
    }

    const float p   = __ldg(&smooth[bp]);
    const float pm1 = p - 1.0f;

    // ---- single fused loop (k=1 speculation), both dirs ----
    float zmax0 = 0.0f, zmax1 = 0.0f;
    float s0 = 0.f, wx0 = 0.f, wy0 = 0.f, wz0 = 0.f;
    float s1 = 0.f, wx1 = 0.f, wy1 = 0.f, wz1 = 0.f;

    #pragma unroll 8
    for (int v = 0; v < NV; v++) {
        float4 lv = slv[v];
        {
            float z  = fmaf(lv.x, ax, fmaf(lv.y, ay, lv.z * az));
            float zm = fmaxf(z, 0.0f);
            zmax0 = fmaxf(zmax0, zm);
            float l  = __log2f(zm);             // -inf when zm==0
            float w  = exp2f(pm1 * l);          // zm^(p-1); 0 for zm==0
            float zp = fmaxf(w * zm, 1e-20f);
            s0 += (z > 0.0f) ? zp : 0.0f;
            wx0 = fmaf(w, lv.x, wx0);
            wy0 = fmaf(w, lv.y, wy0);
            wz0 = fmaf(w, lv.z, wz0);
        }
        {
            float z  = fmaf(lv.x, bx, fmaf(lv.y, by, lv.z * bz));
            float zm = fmaxf(z, 0.0f);
            zmax1 = fmaxf(zmax1, zm);
            float l  = __log2f(zm);
            float w  = exp2f(pm1 * l);
            float zp = fmaxf(w * zm, 1e-20f);
            s1 += (z > 0.0f) ? zp : 0.0f;
            wx1 = fmaf(w, lv.x, wx1);
            wy1 = fmaf(w, lv.y, wy1);
            wz1 = fmaf(w, lv.z, wz1);
        }
    }

    const float invp = 1.0f / p;
    const float omp  = 1.0f - p;

    // ---- k check + epilogue, dir 0 ----
    {
        float k0 = 1.0f;
        float h, scale;
        if (zmax0 > 0.0f) {
            float expo = log10f(zmax0) * p;
            if (expo < -20.0f) {   // rare: redo with proper k
                float ke = fminf(fmaxf(ceilf((-20.0f - expo) / p), 0.0f), 20.0f);
                k0 = c_pow10[(int)ke];
                redo_dir(slv, pm1, k0, ax, ay, az, s0, wx0, wy0, wz0);
            }
            h = exp2f(__log2f(s0) * invp);
            h = fminf(fmaxf(h, 1e-20f), 1e20f);
            scale = exp2f(omp * __log2f(h));
        } else {
            k0 = 1e20f; h = 1e-20f; scale = 0.0f;
            wx0 = wy0 = wz0 = 0.0f;
        }
        size_t pidx = ((size_t)bp * NDIR + d0) * 3;
        out[OFF_POINTS + pidx + 0] = fmaf(wx0, scale, mx);
        out[OFF_POINTS + pidx + 1] = fmaf(wy0, scale, my);
        out[OFF_POINTS + pidx + 2] = fmaf(wz0, scale, mz);
        ((float4*)(out + OFF_DH))[(size_t)bp * NDIR + d0] =
            make_float4(ax, ay, az, h / k0);
    }
    // ---- dir 1 ----
    if (has1) {
        float k1 = 1.0f;
        float h, scale;
        if (zmax1 > 0.0f) {
            float expo = log10f(zmax1) * p;
            if (expo < -20.0f) {
                float ke = fminf(fmaxf(ceilf((-20.0f - expo) / p), 0.0f), 20.0f);
                k1 = c_pow10[(int)ke];
                redo_dir(slv, pm1, k1, bx, by, bz, s1, wx1, wy1, wz1);
            }
            h = exp2f(__log2f(s1) * invp);
            h = fminf(fmaxf(h, 1e-20f), 1e20f);
            scale = exp2f(omp * __log2f(h));
        } else {
            k1 = 1e20f; h = 1e-20f; scale = 0.0f;
            wx1 = wy1 = wz1 = 0.0f;
        }
        size_t pidx = ((size_t)bp * NDIR + d1) * 3;
        out[OFF_POINTS + pidx + 0] = fmaf(wx1, scale, mx);
        out[OFF_POINTS + pidx + 1] = fmaf(wy1, scale, my);
        out[OFF_POINTS + pidx + 2] = fmaf(wz1, scale, mz);
        ((float4*)(out + OFF_DH))[(size_t)bp * NDIR + d1] =
            make_float4(bx, by, bz, h / k1);
    }
}

// ---------------------------------------------------------------------------
extern "C" void kernel_launch(void* const* d_in, const int* in_sizes, int n_in,
                              void* d_out, int out_size) {
    const float* verts  = (const float*)d_in[0];
    const float* smooth = (const float*)d_in[1];
    float* out = (float*)d_out;

    fused_kernel<<<dim3(NCH, NBP), TPB>>>(verts, smooth, out);
}